// round 14
// baseline (speedup 1.0000x reference)
#include <cuda_runtime.h>
#include <cuda_fp16.h>

// WordHashing: sparse [B=16384 x 30000] (COO, rows sorted) @ W [30000 x 300] + bias, ReLU.
// R13 post-mortem: F2F not the limiter. New model: within-LDG wavefront replays
// (2.07 cyc/wf) on the 4-5-line LDG.128 gather = ~13.5 cyc/nnz -> predicts the
// frozen ~30us. R14: rows padded to 640B (5 x 128B, aligned); each nnz gathered
// by 5x LDG.32 at immediate offsets {0,128,256,384,512} — every LDG = exactly
// one 128B line = one wavefront at the 1.0 cyc cross-LDG rate (5 cyc/nnz).

#define OUT_DIM   300
#define IN_DIM    30000
#define ROW_INT4  40           // 40 x 16B = 640B per padded fp16 row (320 halves)
#define ROW_BYTES 640
#define MAX_BATCH 16384

#define CONV_THREADS 256
#define CONV_BLOCKS  ((IN_DIM * ROW_INT4 + CONV_THREADS - 1) / CONV_THREADS)

__device__ int g_row_start[MAX_BATCH + 1];
__device__ __align__(128) int4 g_Wh4[IN_DIM * ROW_INT4];   // 19.2 MB fp16 staged weights

// ---------------------------------------------------------------------------
// Fused prep: blocks [0, CONV_BLOCKS) convert W f32 -> padded f16 rows (640B);
// remaining blocks build row_start from sorted sp_rows.
__global__ void prep_kernel(const float* __restrict__ W,
                            const int* __restrict__ rows,
                            int nnz, int batch, int conv_blocks_thr) {
    if (blockIdx.x < (unsigned)conv_blocks_thr) {
        const int i = blockIdx.x * CONV_THREADS + threadIdx.x;
        if (i >= IN_DIM * ROW_INT4) return;
        const int row = i / ROW_INT4;
        const int k   = i - row * ROW_INT4;
        const int col = k * 8;

        float4 a = make_float4(0.f, 0.f, 0.f, 0.f);
        float4 b = make_float4(0.f, 0.f, 0.f, 0.f);
        const float4* src = reinterpret_cast<const float4*>(W + (size_t)row * OUT_DIM + col);
        if (col + 8 <= OUT_DIM)      { a = __ldg(src); b = __ldg(src + 1); }
        else if (col < OUT_DIM)      { a = __ldg(src); }   // col==296: cols 296..299

        __align__(16) __half2 hh[4];
        hh[0] = __floats2half2_rn(a.x, a.y);
        hh[1] = __floats2half2_rn(a.z, a.w);
        hh[2] = __floats2half2_rn(b.x, b.y);
        hh[3] = __floats2half2_rn(b.z, b.w);
        g_Wh4[i] = *reinterpret_cast<const int4*>(hh);
    } else {
        const int i = (blockIdx.x - conv_blocks_thr) * CONV_THREADS + threadIdx.x;
        if (i >= nnz) return;
        int r  = rows[i];
        int rp = (i == 0) ? -1 : rows[i - 1];
        for (int q = rp + 1; q <= r; ++q) g_row_start[q] = i;
        if (i == nnz - 1) {
            for (int q = r + 1; q <= batch; ++q) g_row_start[q] = nnz;
        }
    }
}

// ---------------------------------------------------------------------------
// Packed convert+FMA: acc(f32x2) += cvt(f16x2 w2) * vv(f32x2).
__device__ __forceinline__ void cvt_fma2(unsigned long long& acc,
                                         unsigned int w2,
                                         unsigned long long vv) {
    __half2 h;
    *reinterpret_cast<unsigned int*>(&h) = w2;
    const float2 wf = __half22float2(h);            // 2x F2F, selector form
    asm("{\n\t"
        ".reg .b64 wp;\n\t"
        "mov.b64 wp, {%1, %2};\n\t"
        "fma.rn.f32x2 %0, wp, %3, %0;\n\t"
        "}" : "+l"(acc) : "f"(wf.x), "f"(wf.y), "l"(vv));
}

// ---------------------------------------------------------------------------
// spmm: 64-thread CTA = 2 warps, one sparse row each.
// Lane t owns cols {64k + 2t, 64k + 2t + 1 : k=0..4}. Per nnz: 5 x LDG.32 at
// base + c*640 + 4t + 128k — each exactly one 128B line per warp.
__global__ __launch_bounds__(64) void spmm_row_kernel(
    const int*   __restrict__ cols,
    const float* __restrict__ vals,
    const float* __restrict__ bias,
    float*       __restrict__ out,
    int batch)
{
    __shared__ int2 s_cv[2][2][32];
    const int warp = threadIdx.x >> 5;
    const int lane = threadIdx.x & 31;
    const int row  = blockIdx.x * 2 + warp;
    if (row >= batch) return;

    const int start = g_row_start[row];        // uniform -> broadcast LDG
    const int end   = g_row_start[row + 1];

    unsigned long long a0 = 0ull, a1 = 0ull, a2 = 0ull, a3 = 0ull, a4 = 0ull;

    const char* __restrict__ lbase =
        reinterpret_cast<const char*>(g_Wh4) + lane * 4;

    // Prefetch chunk 0.
    int2 pf = make_int2(0, 0);
    if (start + lane < end) {
        pf = make_int2(__ldg(cols + start + lane) * ROW_BYTES,
                       __float_as_int(__ldg(vals + start + lane)));
    }

    int parity = 0;
    for (int base = start; base < end; base += 32, parity ^= 1) {
        const int rem = end - base;
        const int n   = rem < 32 ? rem : 32;
        s_cv[warp][parity][lane] = pf;         // publish current chunk
        __syncwarp();
        const int nb = base + 32;
        if (nb + lane < end) {                 // prefetch next chunk
            pf = make_int2(__ldg(cols + nb + lane) * ROW_BYTES,
                           __float_as_int(__ldg(vals + nb + lane)));
        }
        #pragma unroll 8
        for (int j = 0; j < n; ++j) {
            const int2  cv = s_cv[warp][parity][j];    // LDS.64 broadcast
            const float v  = __int_as_float(cv.y);
            unsigned long long vv;
            asm("mov.b64 %0, {%1, %1};" : "=l"(vv) : "f"(v));
            const int* p = reinterpret_cast<const int*>(lbase + cv.x);
            const int w0 = __ldg(p);                    // +0    (1 line)
            const int w1 = __ldg(p + 32);               // +128B (1 line)
            const int w2 = __ldg(p + 64);               // +256B
            const int w3 = __ldg(p + 96);               // +384B
            const int w4 = __ldg(p + 128);              // +512B (pad-covered)
            cvt_fma2(a0, (unsigned)w0, vv);
            cvt_fma2(a1, (unsigned)w1, vv);
            cvt_fma2(a2, (unsigned)w2, vv);
            cvt_fma2(a3, (unsigned)w3, vv);
            cvt_fma2(a4, (unsigned)w4, vv);
        }
    }

    float acc[10];
    asm("mov.b64 {%0, %1}, %2;" : "=f"(acc[0]), "=f"(acc[1]) : "l"(a0));
    asm("mov.b64 {%0, %1}, %2;" : "=f"(acc[2]), "=f"(acc[3]) : "l"(a1));
    asm("mov.b64 {%0, %1}, %2;" : "=f"(acc[4]), "=f"(acc[5]) : "l"(a2));
    asm("mov.b64 {%0, %1}, %2;" : "=f"(acc[6]), "=f"(acc[7]) : "l"(a3));
    asm("mov.b64 {%0, %1}, %2;" : "=f"(acc[8]), "=f"(acc[9]) : "l"(a4));

    // Epilogue: +bias, ReLU. Lane t stores float2 at cols 64k + 2t (k=0..4).
    float* orow = out + (size_t)row * OUT_DIM;
    #pragma unroll
    for (int k = 0; k < 5; ++k) {
        const int c = 64 * k + 2 * lane;
        if (k < 4 || c < OUT_DIM) {            // k==4: lanes 0..21 only
            const float2 b = __ldg(reinterpret_cast<const float2*>(bias + c));
            float2 o;
            o.x = fmaxf(acc[2 * k]     + b.x, 0.f);
            o.y = fmaxf(acc[2 * k + 1] + b.y, 0.f);
            *reinterpret_cast<float2*>(orow + c) = o;
        }
    }
}

extern "C" void kernel_launch(void* const* d_in, const int* in_sizes, int n_in,
                              void* d_out, int out_size) {
    const int*   sp_rows = (const int*)  d_in[0];
    const int*   sp_cols = (const int*)  d_in[1];
    const float* sp_vals = (const float*)d_in[2];
    const float* weights = (const float*)d_in[3];
    const float* bias    = (const float*)d_in[4];

    const int nnz   = in_sizes[0];
    const int batch = out_size / OUT_DIM;

    const int build_blocks = (nnz + CONV_THREADS - 1) / CONV_THREADS;
    prep_kernel<<<CONV_BLOCKS + build_blocks, CONV_THREADS>>>(
        weights, sp_rows, nnz, batch, CONV_BLOCKS);
    spmm_row_kernel<<<(batch + 1) / 2, 64>>>(sp_cols, sp_vals, bias,
                                             (float*)d_out, batch);
}

// round 15
// speedup vs baseline: 1.1633x; 1.1633x over previous
#include <cuda_runtime.h>
#include <cuda_fp16.h>

// WordHashing: sparse [B=16384 x 30000] (COO, rows sorted) @ W [30000 x 300] + bias, ReLU.
// R14 post-mortem: 5xLDG.32 hit the LDG->LDG 4-cyc structural floor (regressed);
// 2-LDG R12 shape restored. Surviving observation: achieved occ 50.7% vs 65.6%
// theoretical — wave/straggler loss. R15: persistent grid (148x21 CTAs, full
// residency), grid-stride rows per warp; inner loop identical to R12.

#define OUT_DIM   300
#define IN_DIM    30000
#define ROW_INT4  38           // 38 x 16B = 608B per padded fp16 row (304 halves)
#define ROW_BYTES 608
#define MAX_BATCH 16384

#define CONV_THREADS 256
#define CONV_BLOCKS  ((IN_DIM * ROW_INT4 + CONV_THREADS - 1) / CONV_THREADS)

#define SPMM_CTAS   3108       // 148 SMs x 21 resident CTAs (48 regs, 64 thr)
#define SPMM_WARPS  (SPMM_CTAS * 2)

__device__ int g_row_start[MAX_BATCH + 1];
__device__ __align__(128) int4 g_Wh4[IN_DIM * ROW_INT4];   // 18.2 MB fp16 staged weights

// ---------------------------------------------------------------------------
// Fused prep: blocks [0, CONV_BLOCKS) convert W f32 -> padded f16 rows;
// remaining blocks build row_start from sorted sp_rows.
__global__ void prep_kernel(const float* __restrict__ W,
                            const int* __restrict__ rows,
                            int nnz, int batch, int conv_blocks_thr) {
    if (blockIdx.x < (unsigned)conv_blocks_thr) {
        const int i = blockIdx.x * CONV_THREADS + threadIdx.x;
        if (i >= IN_DIM * ROW_INT4) return;
        const int row = i / ROW_INT4;
        const int k   = i - row * ROW_INT4;
        const int col = k * 8;

        float4 a = make_float4(0.f, 0.f, 0.f, 0.f);
        float4 b = make_float4(0.f, 0.f, 0.f, 0.f);
        const float4* src = reinterpret_cast<const float4*>(W + (size_t)row * OUT_DIM + col);
        if (col + 8 <= OUT_DIM)      { a = __ldg(src); b = __ldg(src + 1); }
        else if (col < OUT_DIM)      { a = __ldg(src); }   // k==37: cols 296..299

        __align__(16) __half2 hh[4];
        hh[0] = __floats2half2_rn(a.x, a.y);
        hh[1] = __floats2half2_rn(a.z, a.w);
        hh[2] = __floats2half2_rn(b.x, b.y);
        hh[3] = __floats2half2_rn(b.z, b.w);
        g_Wh4[i] = *reinterpret_cast<const int4*>(hh);
    } else {
        const int i = (blockIdx.x - conv_blocks_thr) * CONV_THREADS + threadIdx.x;
        if (i >= nnz) return;
        int r  = rows[i];
        int rp = (i == 0) ? -1 : rows[i - 1];
        for (int q = rp + 1; q <= r; ++q) g_row_start[q] = i;
        if (i == nnz - 1) {
            for (int q = r + 1; q <= batch; ++q) g_row_start[q] = nnz;
        }
    }
}

// ---------------------------------------------------------------------------
// Packed convert+FMA: acc(f32x2) += cvt(f16x2 w2) * vv(f32x2).
__device__ __forceinline__ void cvt_fma2(unsigned long long& acc,
                                         unsigned int w2,
                                         unsigned long long vv) {
    __half2 h;
    *reinterpret_cast<unsigned int*>(&h) = w2;
    const float2 wf = __half22float2(h);            // 2x F2F, selector form
    asm("{\n\t"
        ".reg .b64 wp;\n\t"
        "mov.b64 wp, {%1, %2};\n\t"
        "fma.rn.f32x2 %0, wp, %3, %0;\n\t"
        "}" : "+l"(acc) : "f"(wf.x), "f"(wf.y), "l"(vv));
}

// ---------------------------------------------------------------------------
// spmm: persistent 64-thread CTAs (2 warps). Each warp grid-strides over rows.
// Per row: R12 inner loop (LDG.128 main + LDG.32 tail per nnz, smem-staged
// (c*608, val) chunks with register prefetch).
__global__ __launch_bounds__(64) void spmm_row_kernel(
    const int*   __restrict__ cols,
    const float* __restrict__ vals,
    const float* __restrict__ bias,
    float*       __restrict__ out,
    int batch)
{
    __shared__ int2 s_cv[2][2][32];
    const int warp  = threadIdx.x >> 5;
    const int lane  = threadIdx.x & 31;
    const int gwarp = blockIdx.x * 2 + warp;

    const char* __restrict__ lbase =
        reinterpret_cast<const char*>(g_Wh4) + lane * 16;
    const int tail_imm = 512 - lane * 16 + lane * 4;   // rowp+512+4*lane rel. to lbase
    const bool has_tail = (lane < 22);

    for (int row = gwarp; row < batch; row += SPMM_WARPS) {
        const int start = g_row_start[row];    // uniform -> broadcast LDG
        const int end   = g_row_start[row + 1];

        unsigned long long a0 = 0ull, a1 = 0ull, a2 = 0ull, a3 = 0ull, a4 = 0ull;

        // Prefetch chunk 0.
        int2 pf = make_int2(0, 0);
        if (start + lane < end) {
            pf = make_int2(__ldg(cols + start + lane) * ROW_BYTES,
                           __float_as_int(__ldg(vals + start + lane)));
        }

        int parity = 0;
        for (int base = start; base < end; base += 32, parity ^= 1) {
            const int rem = end - base;
            const int n   = rem < 32 ? rem : 32;
            s_cv[warp][parity][lane] = pf;     // publish current chunk
            __syncwarp();
            const int nb = base + 32;
            if (nb + lane < end) {             // prefetch next chunk
                pf = make_int2(__ldg(cols + nb + lane) * ROW_BYTES,
                               __float_as_int(__ldg(vals + nb + lane)));
            }
            #pragma unroll 8
            for (int j = 0; j < n; ++j) {
                const int2  cv = s_cv[warp][parity][j];    // LDS.64 broadcast
                const float v  = __int_as_float(cv.y);
                unsigned long long vv;
                asm("mov.b64 %0, {%1, %1};" : "=l"(vv) : "f"(v));
                const char* p = lbase + cv.x;
                const int4 w4 = __ldg(reinterpret_cast<const int4*>(p));
                int w1 = 0;
                if (has_tail) w1 = __ldg(reinterpret_cast<const int*>(p + tail_imm));
                cvt_fma2(a0, (unsigned)w4.x, vv);
                cvt_fma2(a1, (unsigned)w4.y, vv);
                cvt_fma2(a2, (unsigned)w4.z, vv);
                cvt_fma2(a3, (unsigned)w4.w, vv);
                cvt_fma2(a4, (unsigned)w1,   vv);
            }
        }

        float acc[10];
        asm("mov.b64 {%0, %1}, %2;" : "=f"(acc[0]), "=f"(acc[1]) : "l"(a0));
        asm("mov.b64 {%0, %1}, %2;" : "=f"(acc[2]), "=f"(acc[3]) : "l"(a1));
        asm("mov.b64 {%0, %1}, %2;" : "=f"(acc[4]), "=f"(acc[5]) : "l"(a2));
        asm("mov.b64 {%0, %1}, %2;" : "=f"(acc[6]), "=f"(acc[7]) : "l"(a3));
        asm("mov.b64 {%0, %1}, %2;" : "=f"(acc[8]), "=f"(acc[9]) : "l"(a4));

        // Epilogue: +bias, ReLU, coalesced stores.
        float* orow = out + (size_t)row * OUT_DIM;
        const int c0 = lane * 8;               // 0..248
        const float4 b0 = __ldg(reinterpret_cast<const float4*>(bias + c0));
        const float4 b1 = __ldg(reinterpret_cast<const float4*>(bias + c0 + 4));
        float4 o0, o1;
        o0.x = fmaxf(acc[0] + b0.x, 0.f);  o0.y = fmaxf(acc[1] + b0.y, 0.f);
        o0.z = fmaxf(acc[2] + b0.z, 0.f);  o0.w = fmaxf(acc[3] + b0.w, 0.f);
        o1.x = fmaxf(acc[4] + b1.x, 0.f);  o1.y = fmaxf(acc[5] + b1.y, 0.f);
        o1.z = fmaxf(acc[6] + b1.z, 0.f);  o1.w = fmaxf(acc[7] + b1.w, 0.f);
        *reinterpret_cast<float4*>(orow + c0)     = o0;
        *reinterpret_cast<float4*>(orow + c0 + 4) = o1;

        const int c1 = 256 + 2 * lane;         // tail cols; valid while < 300
        if (c1 < OUT_DIM) {                    // lanes 0..21
            const float2 b2 = __ldg(reinterpret_cast<const float2*>(bias + c1));
            float2 o2;
            o2.x = fmaxf(acc[8] + b2.x, 0.f);
            o2.y = fmaxf(acc[9] + b2.y, 0.f);
            *reinterpret_cast<float2*>(orow + c1) = o2;
        }
    }
}

extern "C" void kernel_launch(void* const* d_in, const int* in_sizes, int n_in,
                              void* d_out, int out_size) {
    const int*   sp_rows = (const int*)  d_in[0];
    const int*   sp_cols = (const int*)  d_in[1];
    const float* sp_vals = (const float*)d_in[2];
    const float* weights = (const float*)d_in[3];
    const float* bias    = (const float*)d_in[4];

    const int nnz   = in_sizes[0];
    const int batch = out_size / OUT_DIM;

    const int build_blocks = (nnz + CONV_THREADS - 1) / CONV_THREADS;
    prep_kernel<<<CONV_BLOCKS + build_blocks, CONV_THREADS>>>(
        weights, sp_rows, nnz, batch, CONV_BLOCKS);
    spmm_row_kernel<<<SPMM_CTAS, 64>>>(sp_cols, sp_vals, bias,
                                       (float*)d_out, batch);
}

// round 16
// speedup vs baseline: 1.2313x; 1.0585x over previous
#include <cuda_runtime.h>
#include <cuda_fp16.h>

// WordHashing: sparse [B=16384 x 30000] (COO, rows sorted) @ W [30000 x 300] + bias, ReLU.
// R15 post-mortem: the binding wall is practical L2->L1 bandwidth (~12 TB/s
// measured in R1); 608B/nnz -> 26us floor. R6's simple spmm (no reg prefetch)
// already ran ~26us; R7's prefetch slowed it to ~30us and was carried since.
// R16 = fused prep (R7) + R6 spmm verbatim.

#define OUT_DIM   300
#define IN_DIM    30000
#define ROW_INT4  38           // 38 x 16B = 608B per padded fp16 row (304 halves)
#define ROW_BYTES 608
#define MAX_BATCH 16384

#define CONV_THREADS 256
#define CONV_BLOCKS  ((IN_DIM * ROW_INT4 + CONV_THREADS - 1) / CONV_THREADS)

__device__ int g_row_start[MAX_BATCH + 1];
__device__ __align__(128) int4 g_Wh4[IN_DIM * ROW_INT4];   // 18.2 MB fp16 staged weights

// ---------------------------------------------------------------------------
// Fused prep: blocks [0, CONV_BLOCKS) convert W f32 -> padded f16 rows;
// remaining blocks build row_start from sorted sp_rows.
__global__ void prep_kernel(const float* __restrict__ W,
                            const int* __restrict__ rows,
                            int nnz, int batch, int conv_blocks_thr) {
    if (blockIdx.x < (unsigned)conv_blocks_thr) {
        const int i = blockIdx.x * CONV_THREADS + threadIdx.x;
        if (i >= IN_DIM * ROW_INT4) return;
        const int row = i / ROW_INT4;
        const int k   = i - row * ROW_INT4;
        const int col = k * 8;

        float4 a = make_float4(0.f, 0.f, 0.f, 0.f);
        float4 b = make_float4(0.f, 0.f, 0.f, 0.f);
        const float4* src = reinterpret_cast<const float4*>(W + (size_t)row * OUT_DIM + col);
        if (col + 8 <= OUT_DIM)      { a = __ldg(src); b = __ldg(src + 1); }
        else if (col < OUT_DIM)      { a = __ldg(src); }   // k==37: cols 296..299

        __align__(16) __half2 hh[4];
        hh[0] = __floats2half2_rn(a.x, a.y);
        hh[1] = __floats2half2_rn(a.z, a.w);
        hh[2] = __floats2half2_rn(b.x, b.y);
        hh[3] = __floats2half2_rn(b.z, b.w);
        g_Wh4[i] = *reinterpret_cast<const int4*>(hh);
    } else {
        const int i = (blockIdx.x - conv_blocks_thr) * CONV_THREADS + threadIdx.x;
        if (i >= nnz) return;
        int r  = rows[i];
        int rp = (i == 0) ? -1 : rows[i - 1];
        for (int q = rp + 1; q <= r; ++q) g_row_start[q] = i;
        if (i == nnz - 1) {
            for (int q = r + 1; q <= batch; ++q) g_row_start[q] = nnz;
        }
    }
}

// ---------------------------------------------------------------------------
// Packed convert+FMA: acc(f32x2) += cvt(f16x2 w2) * vv(f32x2).
__device__ __forceinline__ void cvt_fma2(unsigned long long& acc,
                                         unsigned int w2,
                                         unsigned long long vv) {
    __half2 h;
    *reinterpret_cast<unsigned int*>(&h) = w2;
    const float2 wf = __half22float2(h);            // 2x F2F, selector form
    asm("{\n\t"
        ".reg .b64 wp;\n\t"
        "mov.b64 wp, {%1, %2};\n\t"
        "fma.rn.f32x2 %0, wp, %3, %0;\n\t"
        "}" : "+l"(acc) : "f"(wf.x), "f"(wf.y), "l"(vv));
}

// ---------------------------------------------------------------------------
// spmm (R6 shape): 128-thread CTA = 4 independent warps, one sparse row each.
// Lane t owns cols [8t,8t+8) (LDG.128); lanes 0..21 also own cols [256+2t,+2).
// smem stages (c*ROW_BYTES, val) pairs, parity double-buffered, ONE syncwarp
// per chunk, NO register prefetch (prefetch measured -4us slower: R6 vs R7).
__global__ __launch_bounds__(128) void spmm_row_kernel(
    const int*   __restrict__ cols,
    const float* __restrict__ vals,
    const float* __restrict__ bias,
    float*       __restrict__ out,
    int batch)
{
    __shared__ int2 s_cv[4][2][32];
    const int warp = threadIdx.x >> 5;
    const int lane = threadIdx.x & 31;
    const int row  = blockIdx.x * 4 + warp;
    if (row >= batch) return;

    const int start = g_row_start[row];        // uniform -> broadcast LDG
    const int end   = g_row_start[row + 1];

    unsigned long long a0 = 0ull, a1 = 0ull, a2 = 0ull, a3 = 0ull, a4 = 0ull;

    const char* __restrict__ lbase =
        reinterpret_cast<const char*>(g_Wh4) + lane * 16;
    const int tail_imm = 512 - lane * 16 + lane * 4;   // rowp+512+4*lane rel. to lbase
    const bool has_tail = (lane < 22);

    int parity = 0;
    for (int base = start; base < end; base += 32, parity ^= 1) {
        const int rem = end - base;
        const int n   = rem < 32 ? rem : 32;
        if (lane < n) {
            s_cv[warp][parity][lane] =
                make_int2(__ldg(cols + base + lane) * ROW_BYTES,
                          __float_as_int(__ldg(vals + base + lane)));
        }
        __syncwarp();
        #pragma unroll 8
        for (int j = 0; j < n; ++j) {
            const int2  cv = s_cv[warp][parity][j];    // LDS.64 broadcast
            const float v  = __int_as_float(cv.y);
            unsigned long long vv;
            asm("mov.b64 %0, {%1, %1};" : "=l"(vv) : "f"(v));
            const char* p = lbase + cv.x;
            const int4 w4 = __ldg(reinterpret_cast<const int4*>(p));
            int w1 = 0;
            if (has_tail) w1 = __ldg(reinterpret_cast<const int*>(p + tail_imm));
            cvt_fma2(a0, (unsigned)w4.x, vv);
            cvt_fma2(a1, (unsigned)w4.y, vv);
            cvt_fma2(a2, (unsigned)w4.z, vv);
            cvt_fma2(a3, (unsigned)w4.w, vv);
            cvt_fma2(a4, (unsigned)w1,   vv);
        }
    }

    float acc[10];
    asm("mov.b64 {%0, %1}, %2;" : "=f"(acc[0]), "=f"(acc[1]) : "l"(a0));
    asm("mov.b64 {%0, %1}, %2;" : "=f"(acc[2]), "=f"(acc[3]) : "l"(a1));
    asm("mov.b64 {%0, %1}, %2;" : "=f"(acc[4]), "=f"(acc[5]) : "l"(a2));
    asm("mov.b64 {%0, %1}, %2;" : "=f"(acc[6]), "=f"(acc[7]) : "l"(a3));
    asm("mov.b64 {%0, %1}, %2;" : "=f"(acc[8]), "=f"(acc[9]) : "l"(a4));

    // Epilogue: +bias, ReLU, coalesced stores.
    float* orow = out + (size_t)row * OUT_DIM;
    const int c0 = lane * 8;                   // 0..248
    const float4 b0 = __ldg(reinterpret_cast<const float4*>(bias + c0));
    const float4 b1 = __ldg(reinterpret_cast<const float4*>(bias + c0 + 4));
    float4 o0, o1;
    o0.x = fmaxf(acc[0] + b0.x, 0.f);  o0.y = fmaxf(acc[1] + b0.y, 0.f);
    o0.z = fmaxf(acc[2] + b0.z, 0.f);  o0.w = fmaxf(acc[3] + b0.w, 0.f);
    o1.x = fmaxf(acc[4] + b1.x, 0.f);  o1.y = fmaxf(acc[5] + b1.y, 0.f);
    o1.z = fmaxf(acc[6] + b1.z, 0.f);  o1.w = fmaxf(acc[7] + b1.w, 0.f);
    *reinterpret_cast<float4*>(orow + c0)     = o0;
    *reinterpret_cast<float4*>(orow + c0 + 4) = o1;

    const int c1 = 256 + 2 * lane;             // tail cols; valid while < 300
    if (c1 < OUT_DIM) {                        // lanes 0..21
        const float2 b2 = __ldg(reinterpret_cast<const float2*>(bias + c1));
        float2 o2;
        o2.x = fmaxf(acc[8] + b2.x, 0.f);
        o2.y = fmaxf(acc[9] + b2.y, 0.f);
        *reinterpret_cast<float2*>(orow + c1) = o2;
    }
}

extern "C" void kernel_launch(void* const* d_in, const int* in_sizes, int n_in,
                              void* d_out, int out_size) {
    const int*   sp_rows = (const int*)  d_in[0];
    const int*   sp_cols = (const int*)  d_in[1];
    const float* sp_vals = (const float*)d_in[2];
    const float* weights = (const float*)d_in[3];
    const float* bias    = (const float*)d_in[4];

    const int nnz   = in_sizes[0];
    const int batch = out_size / OUT_DIM;

    const int build_blocks = (nnz + CONV_THREADS - 1) / CONV_THREADS;
    prep_kernel<<<CONV_BLOCKS + build_blocks, CONV_THREADS>>>(
        weights, sp_rows, nnz, batch, CONV_BLOCKS);
    spmm_row_kernel<<<(batch + 3) / 4, 128>>>(sp_cols, sp_vals, bias,
                                              (float*)d_out, batch);
}